// round 8
// baseline (speedup 1.0000x reference)
#include <cuda_runtime.h>
#include <cuda_bf16.h>
#include <cstdint>
#include <cfloat>

// ---------------------------------------------------------------------------
// SpanModel: cls, span_repr = spanMLP(spanmax,cls,width), top8(entity sims),
// star-GCN (2 layers). sims via int8 mma.sync filter (global entity scale ->
// pure-int ranking) + exact fp32 refine.
// ---------------------------------------------------------------------------

#define TPB 256
#define A_PAD 65
#define SMEM_FLOATS (256 * A_PAD + 64 * 128)
#define SMEM_BYTES (SMEM_FLOATS * 4)

enum { M_SPAN = 0, M_GCN1 = 1, M_GCN2 = 2 };

static const int NE = 50000;
static const int NEP = 50176;        // padded to 392*128
static const int NROWS = 8192;       // Wmax*B*S
static const int NTILES_SEG = 196;   // tiles per entity segment (392/2)
static const int TILE_BYTES = 32768; // 128 entities x 256 int8
static const int NCAND = 24;         // candidates kept per row per segment

// ------------------------- scratch (device globals) -----------------------
__device__ __align__(16) uint8_t g_ETq8[(size_t)392 * TILE_BYTES]; // packed tiles
__device__ unsigned g_gmax;                    // |entity| max (uint-encoded)
__device__ float g_spanmax[8L * 1024 * 256];   // [w][b][s][h]
__device__ float g_rowbias[32 * 256];          // per (w,b) bias row
__device__ int   g_cand[2L * 8192 * NCAND];    // candidate indices per eseg
__device__ int   g_topk[8192L * 8];            // final sorted top-8 indices
__device__ float g_mixed[65536L * 256];        // star-mixed features
__device__ float g_hbuf[65536L * 256];         // relu hidden

// ------------------------- PTX helpers -------------------------------------
__device__ __forceinline__ uint32_t smem_u32(const void* p) {
    uint32_t a;
    asm("{ .reg .u64 t; cvta.to.shared.u64 t, %1; cvt.u32.u64 %0, t; }"
        : "=r"(a) : "l"(p));
    return a;
}

#define STS128(addr, a, b, c, d) \
    asm volatile("st.shared.v4.b32 [%0], {%1,%2,%3,%4};" \
                 :: "r"(addr), "r"(a), "r"(b), "r"(c), "r"(d) : "memory")

#define MBAR_INIT(addr, cnt) \
    asm volatile("mbarrier.init.shared.b64 [%0], %1;" :: "r"(addr), "r"(cnt) : "memory")
#define MBAR_ARRIVE(addr) \
    asm volatile("mbarrier.arrive.shared.b64 _, [%0];" :: "r"(addr) : "memory")
#define MBAR_EXPECT_TX(addr, bytes) \
    asm volatile("mbarrier.arrive.expect_tx.shared.b64 _, [%0], %1;" \
                 :: "r"(addr), "r"(bytes) : "memory")
#define BULK_LD(dst, src, bytes, mbar) \
    asm volatile("cp.async.bulk.shared::cta.global.mbarrier::complete_tx::bytes " \
                 "[%0], [%1], %2, [%3];" \
                 :: "r"(dst), "l"(src), "r"(bytes), "r"(mbar) : "memory")

__device__ __forceinline__ void waitp(uint32_t mbar, uint32_t phase) {
    asm volatile(
        "{\n\t.reg .pred P;\n\t"
        "WL%=:\n\t"
        "mbarrier.try_wait.parity.acquire.cta.shared::cta.b64 P, [%0], %1, 0x989680;\n\t"
        "@P bra WD%=;\n\t"
        "bra WL%=;\n\t"
        "WD%=:\n\t}"
        :: "r"(mbar), "r"(phase) : "memory");
}

#define LDMX4(r0, r1, r2, r3, addr) \
    asm volatile("ldmatrix.sync.aligned.m8n8.x4.shared.b16 {%0,%1,%2,%3}, [%4];" \
                 : "=r"(r0), "=r"(r1), "=r"(r2), "=r"(r3) : "r"(addr))

#define IMMA16832(c, a0, a1, a2, a3, b0, b1) \
    asm volatile("mma.sync.aligned.m16n8k32.row.col.s32.s8.s8.s32 " \
                 "{%0,%1,%2,%3}, {%4,%5,%6,%7}, {%8,%9}, {%0,%1,%2,%3};" \
                 : "+r"((c)[0]), "+r"((c)[1]), "+r"((c)[2]), "+r"((c)[3]) \
                 : "r"(a0), "r"(a1), "r"(a2), "r"(a3), "r"(b0), "r"(b1))

// blocked SW128 layout for a 128-row x 256-byte tile (32 atoms x 1KB = 32KB)
__device__ __forceinline__ uint32_t tileoff(int r, int cb) {
    int b = ((r >> 3) + (cb >> 7) * 16) * 1024 + (r & 7) * 128 + (cb & 127);
    return (uint32_t)(b ^ ((b >> 3) & 0x70));
}

// ------------------------- top-k helpers -----------------------------------
__device__ __forceinline__ bool better(float v1, int i1, float v2, int i2) {
    return (v1 > v2) || (v1 == v2 && i1 < i2);
}
__device__ __forceinline__ bool better_i(int v1, int i1, int v2, int i2) {
    return (v1 > v2) || (v1 == v2 && i1 < i2);
}

__device__ __forceinline__ void insert8(float tv[8], int ti[8], float v, int e) {
    if (better(v, e, tv[7], ti[7])) {
        tv[7] = v; ti[7] = e;
#pragma unroll
        for (int j = 7; j > 0; --j) {
            if (better(tv[j], ti[j], tv[j - 1], ti[j - 1])) {
                float fv = tv[j]; tv[j] = tv[j - 1]; tv[j - 1] = fv;
                int ii = ti[j]; ti[j] = ti[j - 1]; ti[j - 1] = ii;
            }
        }
    }
}

__device__ __forceinline__ void insert8i(int tv[8], int ti[8], int v, int e) {
    if (better_i(v, e, tv[7], ti[7])) {
        tv[7] = v; ti[7] = e;
#pragma unroll
        for (int j = 7; j > 0; --j) {
            if (better_i(tv[j], ti[j], tv[j - 1], ti[j - 1])) {
                int fv = tv[j]; tv[j] = tv[j - 1]; tv[j - 1] = fv;
                int ii = ti[j]; ti[j] = ti[j - 1]; ti[j - 1] = ii;
            }
        }
    }
}

__device__ __noinline__ void insertN_slow_i(int* tv, int* ti, int n, int v, int e) {
    int q = n - 1;
    while (q > 0 && better_i(v, e, tv[q - 1], ti[q - 1])) {
        tv[q] = tv[q - 1]; ti[q] = ti[q - 1]; --q;
    }
    tv[q] = v; ti[q] = e;
}

// ------------------------- small kernels -----------------------------------

__global__ void k_zero() { if (threadIdx.x == 0) g_gmax = 0u; }

// global |max| of entity table (positive-float bits order as uints)
__global__ void k_gmax(const float* __restrict__ ET) {
    int g = blockIdx.x * 256 + threadIdx.x;
    const float4* p = (const float4*)ET + (size_t)g * 2;
    float4 a = p[0], b = p[1];
    float m = fmaxf(fmaxf(fmaxf(fabsf(a.x), fabsf(a.y)), fmaxf(fabsf(a.z), fabsf(a.w))),
                    fmaxf(fmaxf(fabsf(b.x), fabsf(b.y)), fmaxf(fabsf(b.z), fabsf(b.w))));
#pragma unroll
    for (int o = 16; o; o >>= 1) m = fmaxf(m, __shfl_xor_sync(0xFFFFFFFFu, m, o));
    if ((threadIdx.x & 31) == 0) atomicMax(&g_gmax, __float_as_uint(m));
}

// entity table fp32 -> int8 (GLOBAL scale) packed tile blobs
__global__ void k_etq8(const float* __restrict__ ET) {
    int warp = threadIdx.x >> 5, lane = threadIdx.x & 31;
    int r = blockIdx.x * 8 + warp;          // entity row 0..NEP-1
    float gm = __uint_as_float(g_gmax);
    float inv = (gm > 0.f) ? 127.f / gm : 0.f;
    float x[8];
    if (r < NE) {
        float4 v0 = *(const float4*)&ET[(size_t)r * 256 + lane * 8];
        float4 v1 = *(const float4*)&ET[(size_t)r * 256 + lane * 8 + 4];
        x[0] = v0.x; x[1] = v0.y; x[2] = v0.z; x[3] = v0.w;
        x[4] = v1.x; x[5] = v1.y; x[6] = v1.z; x[7] = v1.w;
    } else {
#pragma unroll
        for (int j = 0; j < 8; ++j) x[j] = 0.f;
    }
    int q[8];
#pragma unroll
    for (int j = 0; j < 8; ++j) q[j] = __float2int_rn(x[j] * inv);
    uint32_t lo = (q[0] & 255) | ((q[1] & 255) << 8) | ((q[2] & 255) << 16) | (q[3] << 24);
    uint32_t hi = (q[4] & 255) | ((q[5] & 255) << 8) | ((q[6] & 255) << 16) | (q[7] << 24);
    uint8_t* tb = g_ETq8 + (size_t)(r >> 7) * TILE_BYTES;
    *(uint2*)(tb + tileoff(r & 127, lane * 8)) = make_uint2(lo, hi);
}

// cls out + running span max over widths 1..8
__global__ void k_spanprep(const float* __restrict__ emb, float* __restrict__ out_cls) {
    int g = blockIdx.x * TPB + threadIdx.x;   // b*65536 + s*256 + h
    int h = g & 255, s = (g >> 8) & 255, b = g >> 16;
    float v0 = emb[g];
    float cur = v0;
    g_spanmax[g] = cur;
#pragma unroll
    for (int w = 1; w < 8; ++w) {
        if (s + w < 256) cur = fmaxf(cur, emb[((size_t)b * 256 + s + w) * 256 + h]);
        g_spanmax[(size_t)w * 262144 + g] = cur;
    }
    if (s == 0) out_cls[b * 256 + h] = v0;
}

// rowbias[w*4+b][h] = span_b[h] + (w+1)*W[512][h] + sum_j cls[b][j]*W[256+j][h]
__global__ void k_rowbias(const float* __restrict__ emb, const float* __restrict__ spanW,
                          const float* __restrict__ spanb) {
    int bw = blockIdx.x;
    int w = bw >> 2, b = bw & 3;
    int h = threadIdx.x;
    __shared__ float cls_s[256];
    cls_s[h] = emb[(size_t)b * 65536 + h];
    __syncthreads();
    float acc = spanb[h] + (float)(w + 1) * spanW[512 * 256 + h];
    for (int j = 0; j < 256; ++j)
        acc = fmaf(cls_s[j], spanW[(256 + j) * 256 + h], acc);
    g_rowbias[bw * 256 + h] = acc;
}

// ------------------------- FFMA GEMM (span/GCN) ----------------------------

__device__ __forceinline__ void fill_a(float* a_sm, const float* __restrict__ A,
                                       int row0, int tid) {
#pragma unroll
    for (int it = 0; it < 16; ++it) {
        int f = tid + 256 * it;
        int r = f >> 6;
        int q = f & 63;
        float4 v = *(const float4*)&A[((size_t)(row0 + r)) * 256 + 4 * q];
        a_sm[(4 * q + 0) * A_PAD + r] = v.x;
        a_sm[(4 * q + 1) * A_PAD + r] = v.y;
        a_sm[(4 * q + 2) * A_PAD + r] = v.z;
        a_sm[(4 * q + 3) * A_PAD + r] = v.w;
    }
}

__device__ __forceinline__ void fill_b(float* b_sm, const float* __restrict__ Bg,
                                       int ldb, int colBase, int kc, int tid) {
#pragma unroll
    for (int it = 0; it < 8; ++it) {
        int f = tid + 256 * it;
        int kk = f >> 5;
        int e4 = f & 31;
        int gc = colBase + 4 * e4;
        float4 v = *(const float4*)&Bg[((size_t)(kc * 64 + kk)) * ldb + gc];
        int cx = ((kk >> 3) & 7) << 2;
        *(float4*)&b_sm[kk * 128 + ((4 * e4) ^ cx)] = v;
    }
}

__device__ __forceinline__ void compute_chunk(const float* __restrict__ a_sm,
                                              const float* __restrict__ b_sm,
                                              float acc[4][8], int kc, int rb, int tc) {
    const int cA = tc * 4;
    const int cB = 64 + tc * 4;
#pragma unroll 8
    for (int kk = 0; kk < 64; ++kk) {
        int kg = kc * 64 + kk;
        float a0 = a_sm[kg * A_PAD + rb + 0];
        float a1 = a_sm[kg * A_PAD + rb + 1];
        float a2 = a_sm[kg * A_PAD + rb + 2];
        float a3 = a_sm[kg * A_PAD + rb + 3];
        int cx = ((kk >> 3) & 7) << 2;
        const float4 b0 = *(const float4*)&b_sm[kk * 128 + (cA ^ cx)];
        const float4 b1 = *(const float4*)&b_sm[kk * 128 + (cB ^ cx)];
        float bj[8] = {b0.x, b0.y, b0.z, b0.w, b1.x, b1.y, b1.z, b1.w};
        float ai[4] = {a0, a1, a2, a3};
#pragma unroll
        for (int i = 0; i < 4; ++i)
#pragma unroll
            for (int j = 0; j < 8; ++j)
                acc[i][j] = fmaf(ai[i], bj[j], acc[i][j]);
    }
}

template <int MODE>
__global__ void __launch_bounds__(256, 2)
gemm_k(const float* __restrict__ A, const float* __restrict__ Bg, int ldb,
       const float* __restrict__ bias, float* __restrict__ C) {
    extern __shared__ float sm[];
    float* a_sm = sm;
    float* b_sm = sm + 256 * A_PAD;
    int tid = threadIdx.x;

    int mt = blockIdx.x >> 1, nt = blockIdx.x & 1;
    int row0 = mt * 64;
    fill_a(a_sm, A, row0, tid);
    __syncthreads();

    int trow = tid >> 4, tc = tid & 15;
    int rb = trow * 4;

    float acc[4][8];
#pragma unroll
    for (int i = 0; i < 4; ++i)
#pragma unroll
        for (int j = 0; j < 8; ++j) acc[i][j] = 0.f;

#pragma unroll 1
    for (int kc = 0; kc < 4; ++kc) {
        if (kc) __syncthreads();
        fill_b(b_sm, Bg, ldb, nt * 128, kc, tid);
        __syncthreads();
        compute_chunk(a_sm, b_sm, acc, kc, rb, tc);
    }

    int c0 = nt * 128 + tc * 4;
    int c1 = c0 + 64;
    if (MODE == M_GCN1 || MODE == M_GCN2) {
        float bv0[4], bv1[4];
#pragma unroll
        for (int j = 0; j < 4; ++j) { bv0[j] = bias[c0 + j]; bv1[j] = bias[c1 + j]; }
#pragma unroll
        for (int i = 0; i < 4; ++i) {
            size_t ro = (size_t)(row0 + rb + i) * 256;
            float o[8];
#pragma unroll
            for (int j = 0; j < 4; ++j) {
                o[j] = acc[i][j] + bv0[j];
                o[4 + j] = acc[i][4 + j] + bv1[j];
            }
            if (MODE == M_GCN1) {
#pragma unroll
                for (int j = 0; j < 8; ++j) o[j] = fmaxf(o[j], 0.f);
            }
            *(float4*)&C[ro + c0] = make_float4(o[0], o[1], o[2], o[3]);
            *(float4*)&C[ro + c1] = make_float4(o[4], o[5], o[6], o[7]);
        }
    } else { // M_SPAN: per-(w,b) row bias
#pragma unroll
        for (int i = 0; i < 4; ++i) {
            int row = row0 + rb + i;
            const float* rbp = bias + ((row >> 8) * 256);
            size_t ro = (size_t)row * 256;
            float o[8];
#pragma unroll
            for (int j = 0; j < 4; ++j) {
                o[j] = acc[i][j] + rbp[c0 + j];
                o[4 + j] = acc[i][4 + j] + rbp[c1 + j];
            }
            *(float4*)&C[ro + c0] = make_float4(o[0], o[1], o[2], o[3]);
            *(float4*)&C[ro + c1] = make_float4(o[4], o[5], o[6], o[7]);
        }
    }
}

// ------------------------- int8 mma sims + top-k filter --------------------
// grid (64 row-tiles, 2 esegs), 512 threads (16 warps).
// smem: A int8 128x256 (32KB) @0, stages 2x32KB @32768/@65536, bars @98304.
// warp w: rows (w>>1)*16..+15, cols (w&1)*64..+63 of each 128x128 tile.

#define STG0 32768
#define STGSZ 32768
#define BARSOFF 98304
#define MK_SMEM (BARSOFF + 64 + 1024)

__global__ void __launch_bounds__(512, 1)
mma_topk(const float* __restrict__ spanrepr) {
    extern __shared__ char rawsm[];
    char* smb = (char*)(((uintptr_t)rawsm + 1023) & ~(uintptr_t)1023);
    uint32_t sbase = smem_u32(smb);
    const uint32_t BARS = sbase + BARSOFF;
    int tid = threadIdx.x;
    int w = tid >> 5, lane = tid & 31;

    int row0 = blockIdx.x * 128;
    int ebase = blockIdx.y * (NTILES_SEG * 128);
    int tbase = blockIdx.y * NTILES_SEG;

    if (tid == 0) {
        MBAR_INIT(BARS + 0, 1);  MBAR_INIT(BARS + 8, 1);    // full (tx-based)
        MBAR_INIT(BARS + 16, 16); MBAR_INIT(BARS + 24, 16); // empty (16 warps)
    }

    // A tile: span_repr rows -> per-row int8 quantization, blocked SW128
    // (per-row scale is a positive constant per row -> rank-invariant, dropped)
    {
        int r = tid >> 2, q = tid & 3;
        const float* rp = spanrepr + (size_t)(row0 + r) * 256 + q * 64;
        float m = 0.f;
#pragma unroll
        for (int i = 0; i < 16; ++i) {
            float4 v = *(const float4*)&rp[i * 4];
            m = fmaxf(m, fmaxf(fmaxf(fabsf(v.x), fabsf(v.y)),
                               fmaxf(fabsf(v.z), fabsf(v.w))));
        }
        m = fmaxf(m, __shfl_xor_sync(0xFFFFFFFFu, m, 1));
        m = fmaxf(m, __shfl_xor_sync(0xFFFFFFFFu, m, 2));
        float inv = (m > 0.f) ? 127.f / m : 0.f;
#pragma unroll
        for (int i = 0; i < 4; ++i) {
            uint32_t u[4];
#pragma unroll
            for (int p = 0; p < 4; ++p) {
                float4 v = *(const float4*)&rp[i * 16 + p * 4];
                int q0 = __float2int_rn(v.x * inv);
                int q1 = __float2int_rn(v.y * inv);
                int q2 = __float2int_rn(v.z * inv);
                int q3 = __float2int_rn(v.w * inv);
                u[p] = (q0 & 255) | ((q1 & 255) << 8) | ((q2 & 255) << 16) | (q3 << 24);
            }
            STS128(sbase + tileoff(r, q * 64 + i * 16), u[0], u[1], u[2], u[3]);
        }
    }
    __syncthreads();

    // prefetch tile 0
    if (tid == 0) {
        MBAR_EXPECT_TX(BARS + 0, (uint32_t)TILE_BYTES);
        BULK_LD(sbase + STG0, (const void*)(g_ETq8 + (size_t)tbase * TILE_BYTES),
                (uint32_t)TILE_BYTES, BARS + 0);
    }

    const int wr = (w >> 1) * 16;
    const int wc = (w & 1) * 64;

    int tv1[8], tv2[8]; int ti1[8], ti2[8];
#pragma unroll
    for (int j = 0; j < 8; ++j) {
        tv1[j] = INT_MIN; ti1[j] = 0x7FFFFFFF;
        tv2[j] = INT_MIN; ti2[j] = 0x7FFFFFFF;
    }

    const int a_r = wr + ((lane >> 3) & 1) * 8 + (lane & 7);
    const int a_cb = ((lane >> 4) & 1) * 16;
    const int b_rbase = wc + ((lane >> 4) & 1) * 8 + (lane & 7);
    const int b_cb = ((lane >> 3) & 1) * 16;

#pragma unroll 1
    for (int i = 0; i < NTILES_SEG; ++i) {
        int s = i & 1, n = i >> 1;
        if (tid == 0 && i + 1 < NTILES_SEG) {
            int j = i + 1, s2 = j & 1;
            if (j >= 2) waitp(BARS + 16 + s2 * 8, ((j >> 1) + 1) & 1);
            MBAR_EXPECT_TX(BARS + 0 + s2 * 8, (uint32_t)TILE_BYTES);
            BULK_LD(sbase + STG0 + s2 * STGSZ,
                    (const void*)(g_ETq8 + (size_t)(tbase + j) * TILE_BYTES),
                    (uint32_t)TILE_BYTES, BARS + 0 + s2 * 8);
        }
        waitp(BARS + 0 + s * 8, n & 1);

        uint32_t bufb = sbase + STG0 + s * STGSZ;
        int acc[8][4];
#pragma unroll
        for (int nf = 0; nf < 8; ++nf)
#pragma unroll
            for (int j = 0; j < 4; ++j) acc[nf][j] = 0;

#pragma unroll
        for (int ks = 0; ks < 8; ++ks) {
            uint32_t a0, a1, a2, a3;
            LDMX4(a0, a1, a2, a3, sbase + tileoff(a_r, ks * 32 + a_cb));
#pragma unroll
            for (int p = 0; p < 4; ++p) {
                uint32_t b0, b1, b2, b3;
                LDMX4(b0, b1, b2, b3,
                      bufb + tileoff(b_rbase + p * 16, ks * 32 + b_cb));
                IMMA16832(acc[2 * p], a0, a1, a2, a3, b0, b1);
                IMMA16832(acc[2 * p + 1], a0, a1, a2, a3, b2, b3);
            }
        }
        __syncwarp();
        if (lane == 0) MBAR_ARRIVE(BARS + 16 + s * 8);  // stage free (acc in regs)

        // fold: pure int ranking (global entity scale is rank-invariant)
        int e0 = ebase + i * 128 + wc + (lane & 3) * 2;
#pragma unroll
        for (int nf = 0; nf < 8; ++nf) {
            int e = e0 + nf * 8;
            insert8i(tv1, ti1, acc[nf][0], e);
            insert8i(tv1, ti1, acc[nf][1], e + 1);
            insert8i(tv2, ti2, acc[nf][2], e);
            insert8i(tv2, ti2, acc[nf][3], e + 1);
        }
    }

    // -------- CTA merge: 8 streams/row -> top-24/row --------
    __syncthreads();
    int* mv = (int*)(smb + STG0);                // [128][64]
    int* mi = (int*)(smb + STG0 + 32768);        // [128][64]
    int sid = (w & 1) * 4 + (lane & 3);
    int r1 = wr + (lane >> 2), r2 = r1 + 8;
#pragma unroll
    for (int j = 0; j < 8; ++j) {
        mv[r1 * 64 + sid * 8 + j] = tv1[j]; mi[r1 * 64 + sid * 8 + j] = ti1[j];
        mv[r2 * 64 + sid * 8 + j] = tv2[j]; mi[r2 * 64 + sid * 8 + j] = ti2[j];
    }
    __syncthreads();
    if (tid < 128) {
        int tv[NCAND]; int ti[NCAND];
#pragma unroll
        for (int j = 0; j < NCAND; ++j) { tv[j] = INT_MIN; ti[j] = 0x7FFFFFFF; }
        for (int q = 0; q < 64; ++q) {
            int v = mv[tid * 64 + q]; int e = mi[tid * 64 + q];
            if (better_i(v, e, tv[NCAND - 1], ti[NCAND - 1]))
                insertN_slow_i(tv, ti, NCAND, v, e);
        }
        int* cp = &g_cand[((size_t)blockIdx.y * 8192 + row0 + tid) * NCAND];
#pragma unroll
        for (int j = 0; j < NCAND; ++j) cp[j] = ti[j];
    }
}

// ------------------------- exact fp32 refine -------------------------------
// one warp per row: 48 candidates, exact dot, top-8 with jax tie-break
__global__ void __launch_bounds__(256)
k_refine(const float* __restrict__ spanrepr, const float* __restrict__ ET) {
    int warp = threadIdx.x >> 5, lane = threadIdx.x & 31;
    int row = blockIdx.x * 8 + warp;

    __shared__ float sims[8][2 * NCAND];
    __shared__ int cidx[8][2 * NCAND];

    if (lane < NCAND) {
        cidx[warp][lane] = g_cand[((size_t)0 * 8192 + row) * NCAND + lane];
        cidx[warp][NCAND + lane] = g_cand[((size_t)1 * 8192 + row) * NCAND + lane];
    }
    float4 a0 = *(const float4*)&spanrepr[(size_t)row * 256 + lane * 8];
    float4 a1 = *(const float4*)&spanrepr[(size_t)row * 256 + lane * 8 + 4];
    __syncwarp();

#pragma unroll 1
    for (int c = 0; c < 2 * NCAND; ++c) {
        int idx = cidx[warp][c];
        const float4* ep = (const float4*)&ET[(size_t)idx * 256 + lane * 8];
        float4 e0 = ep[0], e1 = ep[1];
        float d = a0.x * e0.x + a0.y * e0.y + a0.z * e0.z + a0.w * e0.w
                + a1.x * e1.x + a1.y * e1.y + a1.z * e1.z + a1.w * e1.w;
#pragma unroll
        for (int o = 16; o; o >>= 1) d += __shfl_xor_sync(0xFFFFFFFFu, d, o);
        if (lane == 0) sims[warp][c] = d;
    }
    __syncwarp();
    if (lane == 0) {
        float tv[8]; int ti[8];
#pragma unroll
        for (int j = 0; j < 8; ++j) { tv[j] = -FLT_MAX; ti[j] = 0x7FFFFFFF; }
        for (int c = 0; c < 2 * NCAND; ++c)
            insert8(tv, ti, sims[warp][c], cidx[warp][c]);
#pragma unroll
        for (int j = 0; j < 8; ++j) g_topk[(size_t)row * 8 + j] = ti[j];
    }
}

// ------------------------- GCN mixing ---------------------------------------
__global__ void k_mix1(const float* __restrict__ ET) {
    int n = blockIdx.x, h = threadIdx.x;
    __shared__ int id[8];
    if (h < 8) id[h] = g_topk[n * 8 + h];
    __syncthreads();
    float x0 = ET[(size_t)id[0] * 256 + h];
    float s = 0.f;
    float* outb = g_mixed + (size_t)n * 8 * 256 + h;
#pragma unroll
    for (int j = 1; j < 8; ++j) {
        float xj = ET[(size_t)id[j] * 256 + h];
        s += xj;
        outb[j * 256] = 0.25f * x0 + 0.5f * xj;
    }
    outb[0] = 0.125f * x0 + 0.25f * s;
}

__global__ void k_mix2() {
    int n = blockIdx.x, h = threadIdx.x;
    const float* inb = g_hbuf + (size_t)n * 8 * 256 + h;
    float* outb = g_mixed + (size_t)n * 8 * 256 + h;
    float x0 = inb[0];
    float s = 0.f;
#pragma unroll
    for (int j = 1; j < 8; ++j) {
        float xj = inb[j * 256];
        s += xj;
        outb[j * 256] = 0.25f * x0 + 0.5f * xj;
    }
    outb[0] = 0.125f * x0 + 0.25f * s;
}

// ------------------------- host --------------------------------------------
extern "C" void kernel_launch(void* const* d_in, const int* in_sizes, int n_in,
                              void* d_out, int out_size) {
    const float* emb = (const float*)d_in[0];
    const float* ET = (const float*)d_in[1];
    const float* spanW = (const float*)d_in[2];
    const float* spanb = (const float*)d_in[3];
    const float* W1 = (const float*)d_in[4];
    const float* b1 = (const float*)d_in[5];
    const float* W2 = (const float*)d_in[6];
    const float* b2 = (const float*)d_in[7];

    float* out = (float*)d_out;
    float* out_cls = out;                       // 4*256
    float* out_spanrepr = out + 1024;           // 8192*256
    float* out_sub = out + 1024 + 8192 * 256;   // 65536*256

    float *spanmax, *rowbias, *mixed, *hbuf;
    cudaGetSymbolAddress((void**)&spanmax, g_spanmax);
    cudaGetSymbolAddress((void**)&rowbias, g_rowbias);
    cudaGetSymbolAddress((void**)&mixed, g_mixed);
    cudaGetSymbolAddress((void**)&hbuf, g_hbuf);

    cudaFuncSetAttribute(gemm_k<M_SPAN>, cudaFuncAttributeMaxDynamicSharedMemorySize, SMEM_BYTES);
    cudaFuncSetAttribute(gemm_k<M_GCN1>, cudaFuncAttributeMaxDynamicSharedMemorySize, SMEM_BYTES);
    cudaFuncSetAttribute(gemm_k<M_GCN2>, cudaFuncAttributeMaxDynamicSharedMemorySize, SMEM_BYTES);
    cudaFuncSetAttribute(mma_topk, cudaFuncAttributeMaxDynamicSharedMemorySize, MK_SMEM);

    // 1) global entity max, then int8 pack (padded)
    k_zero<<<1, 32>>>();
    k_gmax<<<6250, 256>>>(ET);
    k_etq8<<<NEP / 8, 256>>>(ET);
    // 2) cls + span max
    k_spanprep<<<1024, TPB>>>(emb, out_cls);
    // 3) per-(w,b) bias rows
    k_rowbias<<<32, TPB>>>(emb, spanW, spanb);
    // 4) span_repr = spanmax @ W[0:256] + rowbias
    gemm_k<M_SPAN><<<256, TPB, SMEM_BYTES>>>(spanmax, spanW, 256, rowbias, out_spanrepr);
    // 5) int8 mma sims + per-eseg top-24 candidate filter
    mma_topk<<<dim3(64, 2), 512, MK_SMEM>>>(out_spanrepr);
    // 6) exact fp32 refine -> sorted top-8
    k_refine<<<1024, 256>>>(out_spanrepr, ET);
    // 7) gather + star mix
    k_mix1<<<NROWS, TPB>>>(ET);
    // 8) hidden = relu(mixed @ W1 + b1)
    gemm_k<M_GCN1><<<2048, TPB, SMEM_BYTES>>>(mixed, W1, 256, b1, hbuf);
    // 9) star mix of hidden
    k_mix2<<<NROWS, TPB>>>();
    // 10) subgraph_out = mixed2 @ W2 + b2
    gemm_k<M_GCN2><<<2048, TPB, SMEM_BYTES>>>(mixed, W2, 256, b2, out_sub);

    (void)in_sizes; (void)n_in; (void)out_size;
}

// round 9
// speedup vs baseline: 1.5028x; 1.5028x over previous
#include <cuda_runtime.h>
#include <cuda_bf16.h>
#include <cstdint>
#include <cfloat>

// ---------------------------------------------------------------------------
// SpanModel: cls, span_repr = spanMLP(spanmax,cls,width), top8(entity sims),
// star-GCN (2 layers). sims via bf16 mma.sync filter (bulk-DMA B tiles)
// + exact fp32 refine. GCN reassociated: Y=ET@W1 precompute, Z=h@W2 + fused mix.
// ---------------------------------------------------------------------------

#define TPB 256
#define A_PAD 65
#define SMEM_FLOATS (256 * A_PAD + 64 * 128)
#define SMEM_BYTES (SMEM_FLOATS * 4)

enum { M_SPAN = 0, M_PLAIN = 1 };

static const int NE = 50000;
static const int NEP = 50176;        // padded to 392*128
static const int NROWS = 8192;       // Wmax*B*S
static const int NTILES_SEG = 196;   // tiles per entity segment (392/2)

// ------------------------- scratch (device globals) -----------------------
__device__ __align__(16) uint8_t g_ETraw[(size_t)NEP * 512]; // bf16, tile-blocked SW128
__device__ float g_spanmax[8L * 1024 * 256];   // [w][b][s][h]
__device__ float g_rowbias[32 * 256];          // per (w,b) bias row
__device__ int   g_cand[2L * 8192 * 16];       // candidate indices per eseg
__device__ int   g_topk[8192L * 8];            // final sorted top-8 indices
__device__ float g_ybuf[(size_t)NEP * 256];    // Y = ET @ W1
__device__ float g_hbuf[65536L * 256];         // relu hidden
__device__ float g_zbuf[65536L * 256];         // Z = h @ W2

// ------------------------- PTX helpers -------------------------------------
__device__ __forceinline__ uint32_t smem_u32(const void* p) {
    uint32_t a;
    asm("{ .reg .u64 t; cvta.to.shared.u64 t, %1; cvt.u32.u64 %0, t; }"
        : "=r"(a) : "l"(p));
    return a;
}

#define STS32(addr, v) \
    asm volatile("st.shared.b32 [%0], %1;" :: "r"(addr), "r"(v) : "memory")

#define MBAR_INIT(addr, cnt) \
    asm volatile("mbarrier.init.shared.b64 [%0], %1;" :: "r"(addr), "r"(cnt) : "memory")
#define MBAR_ARRIVE(addr) \
    asm volatile("mbarrier.arrive.shared.b64 _, [%0];" :: "r"(addr) : "memory")
#define MBAR_EXPECT_TX(addr, bytes) \
    asm volatile("mbarrier.arrive.expect_tx.shared.b64 _, [%0], %1;" \
                 :: "r"(addr), "r"(bytes) : "memory")
#define BULK_LD(dst, src, bytes, mbar) \
    asm volatile("cp.async.bulk.shared::cta.global.mbarrier::complete_tx::bytes " \
                 "[%0], [%1], %2, [%3];" \
                 :: "r"(dst), "l"(src), "r"(bytes), "r"(mbar) : "memory")

__device__ __forceinline__ void waitp(uint32_t mbar, uint32_t phase) {
    asm volatile(
        "{\n\t.reg .pred P;\n\t"
        "WL%=:\n\t"
        "mbarrier.try_wait.parity.acquire.cta.shared::cta.b64 P, [%0], %1, 0x989680;\n\t"
        "@P bra WD%=;\n\t"
        "bra WL%=;\n\t"
        "WD%=:\n\t}"
        :: "r"(mbar), "r"(phase) : "memory");
}

#define LDMX4(r0, r1, r2, r3, addr) \
    asm volatile("ldmatrix.sync.aligned.m8n8.x4.shared.b16 {%0,%1,%2,%3}, [%4];" \
                 : "=r"(r0), "=r"(r1), "=r"(r2), "=r"(r3) : "r"(addr))

#define MMA16816(c, a0, a1, a2, a3, b0, b1) \
    asm volatile("mma.sync.aligned.m16n8k16.row.col.f32.bf16.bf16.f32 " \
                 "{%0,%1,%2,%3}, {%4,%5,%6,%7}, {%8,%9}, {%0,%1,%2,%3};" \
                 : "+f"((c)[0]), "+f"((c)[1]), "+f"((c)[2]), "+f"((c)[3]) \
                 : "r"(a0), "r"(a1), "r"(a2), "r"(a3), "r"(b0), "r"(b1))

// blocked SW128 layout for a 128-row x 512-byte bf16 tile (64 atoms x 1KB)
__device__ __forceinline__ uint32_t tileoff(int r, int cb) {
    int b = ((r >> 3) + (cb >> 7) * 16) * 1024 + (r & 7) * 128 + (cb & 127);
    return (uint32_t)(b ^ ((b >> 3) & 0x70));
}

// ------------------------- top-k helpers -----------------------------------
__device__ __forceinline__ bool better(float v1, int i1, float v2, int i2) {
    return (v1 > v2) || (v1 == v2 && i1 < i2);
}

__device__ __forceinline__ void insert8(float tv[8], int ti[8], float v, int e) {
    if (better(v, e, tv[7], ti[7])) {
        tv[7] = v; ti[7] = e;
#pragma unroll
        for (int j = 7; j > 0; --j) {
            if (better(tv[j], ti[j], tv[j - 1], ti[j - 1])) {
                float fv = tv[j]; tv[j] = tv[j - 1]; tv[j - 1] = fv;
                int ii = ti[j]; ti[j] = ti[j - 1]; ti[j - 1] = ii;
            }
        }
    }
}

__device__ __noinline__ void insert16_slow(float* tv, int* ti, float v, int e) {
    int q = 15;
    while (q > 0 && better(v, e, tv[q - 1], ti[q - 1])) {
        tv[q] = tv[q - 1]; ti[q] = ti[q - 1]; --q;
    }
    tv[q] = v; ti[q] = e;
}

// ------------------------- fused prep kernel -------------------------------
// blocks [0,6272): entity fp32 -> bf16 tile-blocked SW128 (padded rows zero)
// blocks [6272,7296): cls + running span max
// blocks [7296,7328): per-(w,b) bias rows
__global__ void k_prep(const float* __restrict__ emb, const float* __restrict__ ET,
                       const float* __restrict__ spanW, const float* __restrict__ spanb,
                       float* __restrict__ out_cls) {
    int blk = blockIdx.x;
    if (blk < 6272) {
        int g = blk * 256 + threadIdx.x;   // one 16B output chunk
        int r = g >> 5, ch = g & 31;
        uint4 o = make_uint4(0u, 0u, 0u, 0u);
        if (r < NE) {
            const float4* s = (const float4*)&ET[(size_t)r * 256 + ch * 8];
            float4 v0 = s[0], v1 = s[1];
            __nv_bfloat162 p0 = {__float2bfloat16(v0.x), __float2bfloat16(v0.y)};
            __nv_bfloat162 p1 = {__float2bfloat16(v0.z), __float2bfloat16(v0.w)};
            __nv_bfloat162 p2 = {__float2bfloat16(v1.x), __float2bfloat16(v1.y)};
            __nv_bfloat162 p3 = {__float2bfloat16(v1.z), __float2bfloat16(v1.w)};
            o = make_uint4(*(uint32_t*)&p0, *(uint32_t*)&p1,
                           *(uint32_t*)&p2, *(uint32_t*)&p3);
        }
        size_t tile = (size_t)(r >> 7);
        *(uint4*)(g_ETraw + tile * 65536 + tileoff(r & 127, ch * 16)) = o;
    } else if (blk < 7296) {
        int g = (blk - 6272) * 256 + threadIdx.x;   // b*65536 + s*256 + h
        int h = g & 255, s = (g >> 8) & 255, b = g >> 16;
        float v0 = emb[g];
        float cur = v0;
        g_spanmax[g] = cur;
#pragma unroll
        for (int w = 1; w < 8; ++w) {
            if (s + w < 256) cur = fmaxf(cur, emb[((size_t)b * 256 + s + w) * 256 + h]);
            g_spanmax[(size_t)w * 262144 + g] = cur;
        }
        if (s == 0) out_cls[b * 256 + h] = v0;
    } else {
        int bw = blk - 7296;
        int w = bw >> 2, b = bw & 3;
        int h = threadIdx.x;
        __shared__ float cls_s[256];
        cls_s[h] = emb[(size_t)b * 65536 + h];
        __syncthreads();
        float acc = spanb[h] + (float)(w + 1) * spanW[512 * 256 + h];
        for (int j = 0; j < 256; ++j)
            acc = fmaf(cls_s[j], spanW[(256 + j) * 256 + h], acc);
        g_rowbias[bw * 256 + h] = acc;
    }
}

// ------------------------- FFMA GEMM ----------------------------------------

__device__ __forceinline__ void fill_a(float* a_sm, const float* __restrict__ A,
                                       int row0, int tid, int rowmax) {
#pragma unroll
    for (int it = 0; it < 16; ++it) {
        int f = tid + 256 * it;
        int r = f >> 6;
        int q = f & 63;
        int rr = min(row0 + r, rowmax);
        float4 v = *(const float4*)&A[(size_t)rr * 256 + 4 * q];
        a_sm[(4 * q + 0) * A_PAD + r] = v.x;
        a_sm[(4 * q + 1) * A_PAD + r] = v.y;
        a_sm[(4 * q + 2) * A_PAD + r] = v.z;
        a_sm[(4 * q + 3) * A_PAD + r] = v.w;
    }
}

__device__ __forceinline__ void fill_b(float* b_sm, const float* __restrict__ Bg,
                                       int ldb, int colBase, int kc, int tid) {
#pragma unroll
    for (int it = 0; it < 8; ++it) {
        int f = tid + 256 * it;
        int kk = f >> 5;
        int e4 = f & 31;
        int gc = colBase + 4 * e4;
        float4 v = *(const float4*)&Bg[((size_t)(kc * 64 + kk)) * ldb + gc];
        int cx = ((kk >> 3) & 7) << 2;
        *(float4*)&b_sm[kk * 128 + ((4 * e4) ^ cx)] = v;
    }
}

__device__ __forceinline__ void compute_chunk(const float* __restrict__ a_sm,
                                              const float* __restrict__ b_sm,
                                              float acc[4][8], int kc, int rb, int tc) {
    const int cA = tc * 4;
    const int cB = 64 + tc * 4;
#pragma unroll 8
    for (int kk = 0; kk < 64; ++kk) {
        int kg = kc * 64 + kk;
        float a0 = a_sm[kg * A_PAD + rb + 0];
        float a1 = a_sm[kg * A_PAD + rb + 1];
        float a2 = a_sm[kg * A_PAD + rb + 2];
        float a3 = a_sm[kg * A_PAD + rb + 3];
        int cx = ((kk >> 3) & 7) << 2;
        const float4 b0 = *(const float4*)&b_sm[kk * 128 + (cA ^ cx)];
        const float4 b1 = *(const float4*)&b_sm[kk * 128 + (cB ^ cx)];
        float bj[8] = {b0.x, b0.y, b0.z, b0.w, b1.x, b1.y, b1.z, b1.w};
        float ai[4] = {a0, a1, a2, a3};
#pragma unroll
        for (int i = 0; i < 4; ++i)
#pragma unroll
            for (int j = 0; j < 8; ++j)
                acc[i][j] = fmaf(ai[i], bj[j], acc[i][j]);
    }
}

template <int MODE>
__global__ void __launch_bounds__(256, 2)
gemm_k(const float* __restrict__ A, const float* __restrict__ Bg, int ldb,
       const float* __restrict__ bias, float* __restrict__ C, int rowmax) {
    extern __shared__ float sm[];
    float* a_sm = sm;
    float* b_sm = sm + 256 * A_PAD;
    int tid = threadIdx.x;

    int mt = blockIdx.x >> 1, nt = blockIdx.x & 1;
    int row0 = mt * 64;
    fill_a(a_sm, A, row0, tid, rowmax);
    __syncthreads();

    int trow = tid >> 4, tc = tid & 15;
    int rb = trow * 4;

    float acc[4][8];
#pragma unroll
    for (int i = 0; i < 4; ++i)
#pragma unroll
        for (int j = 0; j < 8; ++j) acc[i][j] = 0.f;

#pragma unroll 1
    for (int kc = 0; kc < 4; ++kc) {
        if (kc) __syncthreads();
        fill_b(b_sm, Bg, ldb, nt * 128, kc, tid);
        __syncthreads();
        compute_chunk(a_sm, b_sm, acc, kc, rb, tc);
    }

    int c0 = nt * 128 + tc * 4;
    int c1 = c0 + 64;
    if (MODE == M_PLAIN) {
#pragma unroll
        for (int i = 0; i < 4; ++i) {
            size_t ro = (size_t)(row0 + rb + i) * 256;
            *(float4*)&C[ro + c0] =
                make_float4(acc[i][0], acc[i][1], acc[i][2], acc[i][3]);
            *(float4*)&C[ro + c1] =
                make_float4(acc[i][4], acc[i][5], acc[i][6], acc[i][7]);
        }
    } else { // M_SPAN: per-(w,b) row bias
#pragma unroll
        for (int i = 0; i < 4; ++i) {
            int row = row0 + rb + i;
            const float* rbp = bias + ((row >> 8) * 256);
            size_t ro = (size_t)row * 256;
            float o[8];
#pragma unroll
            for (int j = 0; j < 4; ++j) {
                o[j] = acc[i][j] + rbp[c0 + j];
                o[4 + j] = acc[i][4 + j] + rbp[c1 + j];
            }
            *(float4*)&C[ro + c0] = make_float4(o[0], o[1], o[2], o[3]);
            *(float4*)&C[ro + c1] = make_float4(o[4], o[5], o[6], o[7]);
        }
    }
}

// ------------------------- bf16 mma sims + top-k filter --------------------
// grid (64 row-tiles, 2 esegs), 512 threads (16 warps).
// smem: A bf16 128x256 (64KB) @0, B stages 2x64KB @64KB (bulk-DMA'd), bars @192KB.

#define MK_SMEM (1024 + 196608 + 128)

__global__ void __launch_bounds__(512, 1)
mma_topk(const float* __restrict__ spanrepr) {
    extern __shared__ char rawsm[];
    char* smb = (char*)(((uintptr_t)rawsm + 1023) & ~(uintptr_t)1023);
    uint32_t sbase = smem_u32(smb);
    const uint32_t BARS = sbase + 196608;
    int tid = threadIdx.x;
    int w = tid >> 5, lane = tid & 31;

    int row0 = blockIdx.x * 128;
    int ebase = blockIdx.y * (NTILES_SEG * 128);
    int tbase = blockIdx.y * NTILES_SEG;

    if (tid == 0) {
        MBAR_INIT(BARS + 0, 1);  MBAR_INIT(BARS + 8, 1);    // full (tx-based)
        MBAR_INIT(BARS + 16, 16); MBAR_INIT(BARS + 24, 16); // empty (16 warps)
    }

    // A tile: span_repr rows -> bf16 blocked SW128 layout
    for (int i = tid; i < 128 * 128; i += 512) {
        int r = i >> 7, c = (i & 127) * 2;
        float2 v = *(const float2*)&spanrepr[(size_t)(row0 + r) * 256 + c];
        __nv_bfloat162 bb = {__float2bfloat16(v.x), __float2bfloat16(v.y)};
        STS32(sbase + tileoff(r, c * 2), *(uint32_t*)&bb);
    }
    __syncthreads();

    // prefetch tile 0
    if (tid == 0) {
        MBAR_EXPECT_TX(BARS + 0, 65536u);
        BULK_LD(sbase + 65536, (const void*)(g_ETraw + (size_t)tbase * 65536),
                65536u, BARS + 0);
    }

    const int wr = (w >> 1) * 16;
    const int wc = (w & 1) * 64;

    float tv1[8], tv2[8]; int ti1[8], ti2[8];
#pragma unroll
    for (int j = 0; j < 8; ++j) {
        tv1[j] = -FLT_MAX; ti1[j] = 0x7FFFFFFF;
        tv2[j] = -FLT_MAX; ti2[j] = 0x7FFFFFFF;
    }

    const int a_r = wr + ((lane >> 3) & 1) * 8 + (lane & 7);
    const int a_cb = ((lane >> 4) & 1) * 16;
    const int b_rbase = wc + ((lane >> 4) & 1) * 8 + (lane & 7);
    const int b_cb = ((lane >> 3) & 1) * 16;

#pragma unroll 1
    for (int i = 0; i < NTILES_SEG; ++i) {
        int s = i & 1, n = i >> 1;
        if (tid == 0 && i + 1 < NTILES_SEG) {
            int j = i + 1, s2 = j & 1;
            if (j >= 2) waitp(BARS + 16 + s2 * 8, ((j >> 1) + 1) & 1);
            MBAR_EXPECT_TX(BARS + 0 + s2 * 8, 65536u);
            BULK_LD(sbase + 65536 + s2 * 65536,
                    (const void*)(g_ETraw + (size_t)(tbase + j) * 65536),
                    65536u, BARS + 0 + s2 * 8);
        }
        waitp(BARS + 0 + s * 8, n & 1);

        uint32_t bufb = sbase + 65536 + s * 65536;
        float acc[8][4];
#pragma unroll
        for (int nf = 0; nf < 8; ++nf)
#pragma unroll
            for (int j = 0; j < 4; ++j) acc[nf][j] = 0.f;

#pragma unroll 4
        for (int ks = 0; ks < 16; ++ks) {
            uint32_t a0, a1, a2, a3;
            LDMX4(a0, a1, a2, a3, sbase + tileoff(a_r, ks * 32 + a_cb));
#pragma unroll
            for (int p = 0; p < 4; ++p) {
                uint32_t b0, b1, b2, b3;
                LDMX4(b0, b1, b2, b3,
                      bufb + tileoff(b_rbase + p * 16, ks * 32 + b_cb));
                MMA16816(acc[2 * p], a0, a1, a2, a3, b0, b1);
                MMA16816(acc[2 * p + 1], a0, a1, a2, a3, b2, b3);
            }
        }

        // fold tile results into per-lane top-8 streams (no NE guard: padded)
        int e0 = ebase + i * 128 + wc + (lane & 3) * 2;
#pragma unroll
        for (int nf = 0; nf < 8; ++nf) {
            int e = e0 + nf * 8;
            insert8(tv1, ti1, acc[nf][0], e);
            insert8(tv1, ti1, acc[nf][1], e + 1);
            insert8(tv2, ti2, acc[nf][2], e);
            insert8(tv2, ti2, acc[nf][3], e + 1);
        }
        if (lane == 0) MBAR_ARRIVE(BARS + 16 + s * 8);
    }

    // -------- CTA merge: 8 streams/row -> top-16/row --------
    __syncthreads();
    float* mv = (float*)(smb + 65536);            // [128][64]
    int* mi = (int*)(smb + 65536 + 32768);        // [128][64]
    int sid = (w & 1) * 4 + (lane & 3);
    int r1 = wr + (lane >> 2), r2 = r1 + 8;
#pragma unroll
    for (int j = 0; j < 8; ++j) {
        mv[r1 * 64 + sid * 8 + j] = tv1[j]; mi[r1 * 64 + sid * 8 + j] = ti1[j];
        mv[r2 * 64 + sid * 8 + j] = tv2[j]; mi[r2 * 64 + sid * 8 + j] = ti2[j];
    }
    __syncthreads();
    if (tid < 128) {
        float tv[16]; int ti[16];
#pragma unroll
        for (int j = 0; j < 16; ++j) { tv[j] = -FLT_MAX; ti[j] = 0x7FFFFFFF; }
        for (int q = 0; q < 64; ++q) {
            float v = mv[tid * 64 + q]; int e = mi[tid * 64 + q];
            if (better(v, e, tv[15], ti[15])) insert16_slow(tv, ti, v, e);
        }
        int* cp = &g_cand[((size_t)blockIdx.y * 8192 + row0 + tid) * 16];
#pragma unroll
        for (int j = 0; j < 16; ++j) cp[j] = ti[j];
    }
}

// ------------------------- exact fp32 refine -------------------------------
__global__ void __launch_bounds__(256)
k_refine(const float* __restrict__ spanrepr, const float* __restrict__ ET) {
    int warp = threadIdx.x >> 5, lane = threadIdx.x & 31;
    int row = blockIdx.x * 8 + warp;

    __shared__ float sims[8][32];
    __shared__ int cidx[8][32];

    if (lane < 16) {
        cidx[warp][lane] = g_cand[((size_t)0 * 8192 + row) * 16 + lane];
        cidx[warp][16 + lane] = g_cand[((size_t)1 * 8192 + row) * 16 + lane];
    }
    float4 a0 = *(const float4*)&spanrepr[(size_t)row * 256 + lane * 8];
    float4 a1 = *(const float4*)&spanrepr[(size_t)row * 256 + lane * 8 + 4];
    __syncwarp();

#pragma unroll 1
    for (int c = 0; c < 32; ++c) {
        int idx = cidx[warp][c];
        const float4* ep = (const float4*)&ET[(size_t)idx * 256 + lane * 8];
        float4 e0 = ep[0], e1 = ep[1];
        float d = a0.x * e0.x + a0.y * e0.y + a0.z * e0.z + a0.w * e0.w
                + a1.x * e1.x + a1.y * e1.y + a1.z * e1.z + a1.w * e1.w;
#pragma unroll
        for (int o = 16; o; o >>= 1) d += __shfl_xor_sync(0xFFFFFFFFu, d, o);
        if (lane == 0) sims[warp][c] = d;
    }
    __syncwarp();
    if (lane == 0) {
        float tv[8]; int ti[8];
#pragma unroll
        for (int j = 0; j < 8; ++j) { tv[j] = -FLT_MAX; ti[j] = 0x7FFFFFFF; }
        for (int c = 0; c < 32; ++c) insert8(tv, ti, sims[warp][c], cidx[warp][c]);
#pragma unroll
        for (int j = 0; j < 8; ++j) g_topk[(size_t)row * 8 + j] = ti[j];
    }
}

// ------------------------- GCN fused stages ---------------------------------
// h = relu(star-mix(Y[topk]) + b1)
__global__ void k_gather_mix(const float* __restrict__ b1) {
    int n = blockIdx.x, h = threadIdx.x;
    __shared__ int id[8];
    if (h < 8) id[h] = g_topk[n * 8 + h];
    __syncthreads();
    float bb = b1[h];
    float y0 = g_ybuf[(size_t)id[0] * 256 + h];
    float s = 0.f;
    float* outb = g_hbuf + (size_t)n * 8 * 256 + h;
#pragma unroll
    for (int j = 1; j < 8; ++j) {
        float yj = g_ybuf[(size_t)id[j] * 256 + h];
        s += yj;
        outb[j * 256] = fmaxf(0.25f * y0 + 0.5f * yj + bb, 0.f);
    }
    outb[0] = fmaxf(0.125f * y0 + 0.25f * s + bb, 0.f);
}

// out_sub = star-mix(Z) + b2
__global__ void k_mix_out(const float* __restrict__ b2, float* __restrict__ out_sub) {
    int n = blockIdx.x, h = threadIdx.x;
    const float* inb = g_zbuf + (size_t)n * 8 * 256 + h;
    float* outb = out_sub + (size_t)n * 8 * 256 + h;
    float bb = b2[h];
    float z0 = inb[0];
    float s = 0.f;
#pragma unroll
    for (int j = 1; j < 8; ++j) {
        float zj = inb[j * 256];
        s += zj;
        outb[j * 256] = 0.25f * z0 + 0.5f * zj + bb;
    }
    outb[0] = 0.125f * z0 + 0.25f * s + bb;
}

// ------------------------- host --------------------------------------------
extern "C" void kernel_launch(void* const* d_in, const int* in_sizes, int n_in,
                              void* d_out, int out_size) {
    const float* emb = (const float*)d_in[0];
    const float* ET = (const float*)d_in[1];
    const float* spanW = (const float*)d_in[2];
    const float* spanb = (const float*)d_in[3];
    const float* W1 = (const float*)d_in[4];
    const float* b1 = (const float*)d_in[5];
    const float* W2 = (const float*)d_in[6];
    const float* b2 = (const float*)d_in[7];

    float* out = (float*)d_out;
    float* out_cls = out;                       // 4*256
    float* out_spanrepr = out + 1024;           // 8192*256
    float* out_sub = out + 1024 + 8192 * 256;   // 65536*256

    float *spanmax, *rowbias, *ybuf, *hbuf, *zbuf;
    cudaGetSymbolAddress((void**)&spanmax, g_spanmax);
    cudaGetSymbolAddress((void**)&rowbias, g_rowbias);
    cudaGetSymbolAddress((void**)&ybuf, g_ybuf);
    cudaGetSymbolAddress((void**)&hbuf, g_hbuf);
    cudaGetSymbolAddress((void**)&zbuf, g_zbuf);

    cudaFuncSetAttribute(gemm_k<M_SPAN>, cudaFuncAttributeMaxDynamicSharedMemorySize, SMEM_BYTES);
    cudaFuncSetAttribute(gemm_k<M_PLAIN>, cudaFuncAttributeMaxDynamicSharedMemorySize, SMEM_BYTES);
    cudaFuncSetAttribute(mma_topk, cudaFuncAttributeMaxDynamicSharedMemorySize, MK_SMEM);

    // 1) fused prep: entity bf16 pack + cls/spanmax + rowbias
    k_prep<<<7328, TPB>>>(emb, ET, spanW, spanb, out_cls);
    // 2) span_repr = spanmax @ W[0:256] + rowbias
    gemm_k<M_SPAN><<<256, TPB, SMEM_BYTES>>>(spanmax, spanW, 256, rowbias,
                                             out_spanrepr, NROWS - 1);
    // 3) Y = ET @ W1 (independent of top-k)
    gemm_k<M_PLAIN><<<1568, TPB, SMEM_BYTES>>>(ET, W1, 256, nullptr, ybuf, NE - 1);
    // 4) bf16 mma sims + per-eseg top-16 candidate filter  [profiled launch]
    mma_topk<<<dim3(64, 2), 512, MK_SMEM>>>(out_spanrepr);
    // 5) exact fp32 refine -> sorted top-8
    k_refine<<<1024, 256>>>(out_spanrepr, ET);
    // 6) h = relu(mix(Y[topk]) + b1)
    k_gather_mix<<<NROWS, TPB>>>(b1);
    // 7) Z = h @ W2
    gemm_k<M_PLAIN><<<2048, TPB, SMEM_BYTES>>>(hbuf, W2, 256, nullptr, zbuf, 65535);
    // 8) out_sub = mix(Z) + b2
    k_mix_out<<<NROWS, TPB>>>(b2, out_sub);

    (void)in_sizes; (void)n_in; (void)out_size;
}

// round 10
// speedup vs baseline: 2.1672x; 1.4421x over previous
#include <cuda_runtime.h>
#include <cuda_bf16.h>
#include <cstdint>
#include <cfloat>

// ---------------------------------------------------------------------------
// SpanModel: cls, span_repr = spanMLP(spanmax,cls,width), top8(entity sims),
// star-GCN (2 layers). sims via bf16 mma.sync filter (bulk-DMA B tiles,
// 1024-thread CTAs, packed-key top-8) + exact fp32 refine.
// GCN reassociated: Y=ET@W1 precompute, Z=h@W2 + fused mix.
// ---------------------------------------------------------------------------

#define TPB 256
#define A_PAD 65
#define SMEM_FLOATS (256 * A_PAD + 64 * 128)
#define SMEM_BYTES (SMEM_FLOATS * 4)

enum { M_SPAN = 0, M_PLAIN = 1 };

static const int NE = 50000;
static const int NEP = 50176;        // padded to 392*128
static const int NROWS = 8192;       // Wmax*B*S
static const int NTILES_SEG = 196;   // tiles per entity segment (392/2)

// ------------------------- scratch (device globals) -----------------------
__device__ __align__(16) uint8_t g_ETraw[(size_t)NEP * 512]; // bf16, tile-blocked SW128
__device__ float g_spanmax[8L * 1024 * 256];   // [w][b][s][h]
__device__ float g_rowbias[32 * 256];          // per (w,b) bias row
__device__ int   g_cand[2L * 8192 * 16];       // candidate indices per eseg
__device__ int   g_topk[8192L * 8];            // final sorted top-8 indices
__device__ float g_ybuf[(size_t)NEP * 256];    // Y = ET @ W1
__device__ float g_hbuf[65536L * 256];         // relu hidden
__device__ float g_zbuf[65536L * 256];         // Z = h @ W2

// ------------------------- PTX helpers -------------------------------------
__device__ __forceinline__ uint32_t smem_u32(const void* p) {
    uint32_t a;
    asm("{ .reg .u64 t; cvta.to.shared.u64 t, %1; cvt.u32.u64 %0, t; }"
        : "=r"(a) : "l"(p));
    return a;
}

#define STS32(addr, v) \
    asm volatile("st.shared.b32 [%0], %1;" :: "r"(addr), "r"(v) : "memory")

#define MBAR_INIT(addr, cnt) \
    asm volatile("mbarrier.init.shared.b64 [%0], %1;" :: "r"(addr), "r"(cnt) : "memory")
#define MBAR_ARRIVE(addr) \
    asm volatile("mbarrier.arrive.shared.b64 _, [%0];" :: "r"(addr) : "memory")
#define MBAR_EXPECT_TX(addr, bytes) \
    asm volatile("mbarrier.arrive.expect_tx.shared.b64 _, [%0], %1;" \
                 :: "r"(addr), "r"(bytes) : "memory")
#define BULK_LD(dst, src, bytes, mbar) \
    asm volatile("cp.async.bulk.shared::cta.global.mbarrier::complete_tx::bytes " \
                 "[%0], [%1], %2, [%3];" \
                 :: "r"(dst), "l"(src), "r"(bytes), "r"(mbar) : "memory")

__device__ __forceinline__ void waitp(uint32_t mbar, uint32_t phase) {
    asm volatile(
        "{\n\t.reg .pred P;\n\t"
        "WL%=:\n\t"
        "mbarrier.try_wait.parity.acquire.cta.shared::cta.b64 P, [%0], %1, 0x989680;\n\t"
        "@P bra WD%=;\n\t"
        "bra WL%=;\n\t"
        "WD%=:\n\t}"
        :: "r"(mbar), "r"(phase) : "memory");
}

#define LDMX4(r0, r1, r2, r3, addr) \
    asm volatile("ldmatrix.sync.aligned.m8n8.x4.shared.b16 {%0,%1,%2,%3}, [%4];" \
                 : "=r"(r0), "=r"(r1), "=r"(r2), "=r"(r3) : "r"(addr))

#define MMA16816(c, a0, a1, a2, a3, b0, b1) \
    asm volatile("mma.sync.aligned.m16n8k16.row.col.f32.bf16.bf16.f32 " \
                 "{%0,%1,%2,%3}, {%4,%5,%6,%7}, {%8,%9}, {%0,%1,%2,%3};" \
                 : "+f"((c)[0]), "+f"((c)[1]), "+f"((c)[2]), "+f"((c)[3]) \
                 : "r"(a0), "r"(a1), "r"(a2), "r"(a3), "r"(b0), "r"(b1))

// blocked SW128 layout for a 128-row x 512-byte bf16 tile (64 atoms x 1KB)
__device__ __forceinline__ uint32_t tileoff(int r, int cb) {
    int b = ((r >> 3) + (cb >> 7) * 16) * 1024 + (r & 7) * 128 + (cb & 127);
    return (uint32_t)(b ^ ((b >> 3) & 0x70));
}

// ------------------------- top-k helpers -----------------------------------
__device__ __forceinline__ bool better(float v1, int i1, float v2, int i2) {
    return (v1 > v2) || (v1 == v2 && i1 < i2);
}

__device__ __forceinline__ void insert8(float tv[8], int ti[8], float v, int e) {
    if (better(v, e, tv[7], ti[7])) {
        tv[7] = v; ti[7] = e;
#pragma unroll
        for (int j = 7; j > 0; --j) {
            if (better(tv[j], ti[j], tv[j - 1], ti[j - 1])) {
                float fv = tv[j]; tv[j] = tv[j - 1]; tv[j - 1] = fv;
                int ii = ti[j]; ti[j] = ti[j - 1]; ti[j - 1] = ii;
            }
        }
    }
}

// packed sortable key: [31:15] order-preserving float bits, [14:0] 0x7FFF-eloc
__device__ __forceinline__ uint32_t sortkey(float v, int eloc) {
    uint32_t u = __float_as_uint(v);
    u ^= (uint32_t)((int32_t)u >> 31) | 0x80000000u;
    return (u & 0xFFFF8000u) | (uint32_t)(0x7FFF - eloc);
}

__device__ __forceinline__ void insert8u(uint32_t k[8], uint32_t key) {
    if (key > k[7]) {
        k[7] = key;
#pragma unroll
        for (int j = 7; j > 0; --j) {
            if (k[j] > k[j - 1]) { uint32_t t = k[j]; k[j] = k[j - 1]; k[j - 1] = t; }
        }
    }
}

__device__ __noinline__ void insert16u_slow(uint32_t* tk, uint32_t key) {
    int q = 15;
    while (q > 0 && key > tk[q - 1]) { tk[q] = tk[q - 1]; --q; }
    tk[q] = key;
}

// ------------------------- fused prep kernel -------------------------------
__global__ void k_prep(const float* __restrict__ emb, const float* __restrict__ ET,
                       const float* __restrict__ spanW, const float* __restrict__ spanb,
                       float* __restrict__ out_cls) {
    int blk = blockIdx.x;
    if (blk < 6272) {
        int g = blk * 256 + threadIdx.x;   // one 16B output chunk
        int r = g >> 5, ch = g & 31;
        uint4 o = make_uint4(0u, 0u, 0u, 0u);
        if (r < NE) {
            const float4* s = (const float4*)&ET[(size_t)r * 256 + ch * 8];
            float4 v0 = s[0], v1 = s[1];
            __nv_bfloat162 p0 = {__float2bfloat16(v0.x), __float2bfloat16(v0.y)};
            __nv_bfloat162 p1 = {__float2bfloat16(v0.z), __float2bfloat16(v0.w)};
            __nv_bfloat162 p2 = {__float2bfloat16(v1.x), __float2bfloat16(v1.y)};
            __nv_bfloat162 p3 = {__float2bfloat16(v1.z), __float2bfloat16(v1.w)};
            o = make_uint4(*(uint32_t*)&p0, *(uint32_t*)&p1,
                           *(uint32_t*)&p2, *(uint32_t*)&p3);
        }
        size_t tile = (size_t)(r >> 7);
        *(uint4*)(g_ETraw + tile * 65536 + tileoff(r & 127, ch * 16)) = o;
    } else if (blk < 7296) {
        int g = (blk - 6272) * 256 + threadIdx.x;   // b*65536 + s*256 + h
        int h = g & 255, s = (g >> 8) & 255, b = g >> 16;
        float v0 = emb[g];
        float cur = v0;
        g_spanmax[g] = cur;
#pragma unroll
        for (int w = 1; w < 8; ++w) {
            if (s + w < 256) cur = fmaxf(cur, emb[((size_t)b * 256 + s + w) * 256 + h]);
            g_spanmax[(size_t)w * 262144 + g] = cur;
        }
        if (s == 0) out_cls[b * 256 + h] = v0;
    } else {
        int bw = blk - 7296;
        int w = bw >> 2, b = bw & 3;
        int h = threadIdx.x;
        __shared__ float cls_s[256];
        cls_s[h] = emb[(size_t)b * 65536 + h];
        __syncthreads();
        float acc = spanb[h] + (float)(w + 1) * spanW[512 * 256 + h];
        for (int j = 0; j < 256; ++j)
            acc = fmaf(cls_s[j], spanW[(256 + j) * 256 + h], acc);
        g_rowbias[bw * 256 + h] = acc;
    }
}

// ------------------------- FFMA GEMM ----------------------------------------

__device__ __forceinline__ void fill_a(float* a_sm, const float* __restrict__ A,
                                       int row0, int tid, int rowmax) {
#pragma unroll
    for (int it = 0; it < 16; ++it) {
        int f = tid + 256 * it;
        int r = f >> 6;
        int q = f & 63;
        int rr = min(row0 + r, rowmax);
        float4 v = *(const float4*)&A[(size_t)rr * 256 + 4 * q];
        a_sm[(4 * q + 0) * A_PAD + r] = v.x;
        a_sm[(4 * q + 1) * A_PAD + r] = v.y;
        a_sm[(4 * q + 2) * A_PAD + r] = v.z;
        a_sm[(4 * q + 3) * A_PAD + r] = v.w;
    }
}

__device__ __forceinline__ void fill_b(float* b_sm, const float* __restrict__ Bg,
                                       int ldb, int colBase, int kc, int tid) {
#pragma unroll
    for (int it = 0; it < 8; ++it) {
        int f = tid + 256 * it;
        int kk = f >> 5;
        int e4 = f & 31;
        int gc = colBase + 4 * e4;
        float4 v = *(const float4*)&Bg[((size_t)(kc * 64 + kk)) * ldb + gc];
        int cx = ((kk >> 3) & 7) << 2;
        *(float4*)&b_sm[kk * 128 + ((4 * e4) ^ cx)] = v;
    }
}

__device__ __forceinline__ void compute_chunk(const float* __restrict__ a_sm,
                                              const float* __restrict__ b_sm,
                                              float acc[4][8], int kc, int rb, int tc) {
    const int cA = tc * 4;
    const int cB = 64 + tc * 4;
#pragma unroll 8
    for (int kk = 0; kk < 64; ++kk) {
        int kg = kc * 64 + kk;
        float a0 = a_sm[kg * A_PAD + rb + 0];
        float a1 = a_sm[kg * A_PAD + rb + 1];
        float a2 = a_sm[kg * A_PAD + rb + 2];
        float a3 = a_sm[kg * A_PAD + rb + 3];
        int cx = ((kk >> 3) & 7) << 2;
        const float4 b0 = *(const float4*)&b_sm[kk * 128 + (cA ^ cx)];
        const float4 b1 = *(const float4*)&b_sm[kk * 128 + (cB ^ cx)];
        float bj[8] = {b0.x, b0.y, b0.z, b0.w, b1.x, b1.y, b1.z, b1.w};
        float ai[4] = {a0, a1, a2, a3};
#pragma unroll
        for (int i = 0; i < 4; ++i)
#pragma unroll
            for (int j = 0; j < 8; ++j)
                acc[i][j] = fmaf(ai[i], bj[j], acc[i][j]);
    }
}

template <int MODE>
__global__ void __launch_bounds__(256, 2)
gemm_k(const float* __restrict__ A, const float* __restrict__ Bg, int ldb,
       const float* __restrict__ bias, float* __restrict__ C, int rowmax) {
    extern __shared__ float sm[];
    float* a_sm = sm;
    float* b_sm = sm + 256 * A_PAD;
    int tid = threadIdx.x;

    int mt = blockIdx.x >> 1, nt = blockIdx.x & 1;
    int row0 = mt * 64;
    fill_a(a_sm, A, row0, tid, rowmax);
    __syncthreads();

    int trow = tid >> 4, tc = tid & 15;
    int rb = trow * 4;

    float acc[4][8];
#pragma unroll
    for (int i = 0; i < 4; ++i)
#pragma unroll
        for (int j = 0; j < 8; ++j) acc[i][j] = 0.f;

#pragma unroll 1
    for (int kc = 0; kc < 4; ++kc) {
        if (kc) __syncthreads();
        fill_b(b_sm, Bg, ldb, nt * 128, kc, tid);
        __syncthreads();
        compute_chunk(a_sm, b_sm, acc, kc, rb, tc);
    }

    int c0 = nt * 128 + tc * 4;
    int c1 = c0 + 64;
    if (MODE == M_PLAIN) {
#pragma unroll
        for (int i = 0; i < 4; ++i) {
            size_t ro = (size_t)(row0 + rb + i) * 256;
            *(float4*)&C[ro + c0] =
                make_float4(acc[i][0], acc[i][1], acc[i][2], acc[i][3]);
            *(float4*)&C[ro + c1] =
                make_float4(acc[i][4], acc[i][5], acc[i][6], acc[i][7]);
        }
    } else { // M_SPAN: per-(w,b) row bias
#pragma unroll
        for (int i = 0; i < 4; ++i) {
            int row = row0 + rb + i;
            const float* rbp = bias + ((row >> 8) * 256);
            size_t ro = (size_t)row * 256;
            float o[8];
#pragma unroll
            for (int j = 0; j < 4; ++j) {
                o[j] = acc[i][j] + rbp[c0 + j];
                o[4 + j] = acc[i][4 + j] + rbp[c1 + j];
            }
            *(float4*)&C[ro + c0] = make_float4(o[0], o[1], o[2], o[3]);
            *(float4*)&C[ro + c1] = make_float4(o[4], o[5], o[6], o[7]);
        }
    }
}

// ------------------------- bf16 mma sims + top-k filter --------------------
// grid (64 row-tiles, 2 esegs), 1024 threads (32 warps, 48% occ).
// smem: A bf16 128x256 (64KB) @0, B stages 2x64KB @64KB (bulk-DMA'd), bars @192KB.
// warp w: rows (w>>2)*16..+15, cols (w&3)*32..+31 of each 128x128 tile.

#define MK_SMEM (1024 + 196608 + 128)

__global__ void __launch_bounds__(1024, 1)
mma_topk(const float* __restrict__ spanrepr) {
    extern __shared__ char rawsm[];
    char* smb = (char*)(((uintptr_t)rawsm + 1023) & ~(uintptr_t)1023);
    uint32_t sbase = smem_u32(smb);
    const uint32_t BARS = sbase + 196608;
    int tid = threadIdx.x;
    int w = tid >> 5, lane = tid & 31;

    int row0 = blockIdx.x * 128;
    int ebase = blockIdx.y * (NTILES_SEG * 128);
    int tbase = blockIdx.y * NTILES_SEG;

    if (tid == 0) {
        MBAR_INIT(BARS + 0, 1);  MBAR_INIT(BARS + 8, 1);    // full (tx-based)
        MBAR_INIT(BARS + 16, 32); MBAR_INIT(BARS + 24, 32); // empty (32 warps)
    }

    // A tile: span_repr rows -> bf16 blocked SW128 layout
    for (int i = tid; i < 128 * 128; i += 1024) {
        int r = i >> 7, c = (i & 127) * 2;
        float2 v = *(const float2*)&spanrepr[(size_t)(row0 + r) * 256 + c];
        __nv_bfloat162 bb = {__float2bfloat16(v.x), __float2bfloat16(v.y)};
        STS32(sbase + tileoff(r, c * 2), *(uint32_t*)&bb);
    }
    __syncthreads();

    // prefetch tile 0
    if (tid == 0) {
        MBAR_EXPECT_TX(BARS + 0, 65536u);
        BULK_LD(sbase + 65536, (const void*)(g_ETraw + (size_t)tbase * 65536),
                65536u, BARS + 0);
    }

    const int wr = (w >> 2) * 16;
    const int wc = (w & 3) * 32;

    uint32_t k1[8], k2[8];
#pragma unroll
    for (int j = 0; j < 8; ++j) { k1[j] = 0u; k2[j] = 0u; }

    const int a_r = wr + ((lane >> 3) & 1) * 8 + (lane & 7);
    const int a_cb = ((lane >> 4) & 1) * 16;
    const int b_rbase = wc + ((lane >> 4) & 1) * 8 + (lane & 7);
    const int b_cb = ((lane >> 3) & 1) * 16;

#pragma unroll 1
    for (int i = 0; i < NTILES_SEG; ++i) {
        int s = i & 1, n = i >> 1;
        if (tid == 0 && i + 1 < NTILES_SEG) {
            int j = i + 1, s2 = j & 1;
            if (j >= 2) waitp(BARS + 16 + s2 * 8, ((j >> 1) + 1) & 1);
            MBAR_EXPECT_TX(BARS + 0 + s2 * 8, 65536u);
            BULK_LD(sbase + 65536 + s2 * 65536,
                    (const void*)(g_ETraw + (size_t)(tbase + j) * 65536),
                    65536u, BARS + 0 + s2 * 8);
        }
        waitp(BARS + 0 + s * 8, n & 1);

        uint32_t bufb = sbase + 65536 + s * 65536;
        float acc[4][4];
#pragma unroll
        for (int q = 0; q < 4; ++q)
#pragma unroll
            for (int j = 0; j < 4; ++j) acc[q][j] = 0.f;

#pragma unroll 4
        for (int ks = 0; ks < 16; ++ks) {
            uint32_t a0, a1, a2, a3;
            LDMX4(a0, a1, a2, a3, sbase + tileoff(a_r, ks * 32 + a_cb));
#pragma unroll
            for (int p = 0; p < 2; ++p) {
                uint32_t b0, b1, b2, b3;
                LDMX4(b0, b1, b2, b3,
                      bufb + tileoff(b_rbase + p * 16, ks * 32 + b_cb));
                MMA16816(acc[2 * p], a0, a1, a2, a3, b0, b1);
                MMA16816(acc[2 * p + 1], a0, a1, a2, a3, b2, b3);
            }
        }
        __syncwarp();
        if (lane == 0) MBAR_ARRIVE(BARS + 16 + s * 8);  // acc in regs -> stage free

        // fold: packed sortable keys, top-8 per (lane,row-stream)
        int ebloc = i * 128 + wc + (lane & 3) * 2;
#pragma unroll
        for (int q = 0; q < 4; ++q) {
            int el = ebloc + q * 8;
            insert8u(k1, sortkey(acc[q][0], el));
            insert8u(k1, sortkey(acc[q][1], el + 1));
            insert8u(k2, sortkey(acc[q][2], el));
            insert8u(k2, sortkey(acc[q][3], el + 1));
        }
    }

    // -------- CTA merge: 16 streams/row -> top-16/row --------
    __syncthreads();
    uint32_t* mk = (uint32_t*)(smb + 65536);      // [128][128] keys (64KB)
    int sid = (w & 3) * 4 + (lane & 3);
    int r1 = wr + (lane >> 2), r2 = r1 + 8;
#pragma unroll
    for (int j = 0; j < 8; ++j) {
        mk[r1 * 128 + sid * 8 + j] = k1[j];
        mk[r2 * 128 + sid * 8 + j] = k2[j];
    }
    __syncthreads();
    if (tid < 128) {
        uint32_t tk[16];
#pragma unroll
        for (int j = 0; j < 16; ++j) tk[j] = 0u;
        for (int q = 0; q < 128; ++q) {
            uint32_t key = mk[tid * 128 + q];
            if (key > tk[15]) insert16u_slow(tk, key);
        }
        int* cp = &g_cand[((size_t)blockIdx.y * 8192 + row0 + tid) * 16];
#pragma unroll
        for (int j = 0; j < 16; ++j) {
            int e = ebase + (0x7FFF - (int)(tk[j] & 0x7FFFu));
            cp[j] = (e < NE) ? e : 0;   // clamp (padded sims never win anyway)
        }
    }
}

// ------------------------- exact fp32 refine -------------------------------
__global__ void __launch_bounds__(256)
k_refine(const float* __restrict__ spanrepr, const float* __restrict__ ET) {
    int warp = threadIdx.x >> 5, lane = threadIdx.x & 31;
    int row = blockIdx.x * 8 + warp;

    __shared__ float sims[8][32];
    __shared__ int cidx[8][32];

    if (lane < 16) {
        cidx[warp][lane] = g_cand[((size_t)0 * 8192 + row) * 16 + lane];
        cidx[warp][16 + lane] = g_cand[((size_t)1 * 8192 + row) * 16 + lane];
    }
    float4 a0 = *(const float4*)&spanrepr[(size_t)row * 256 + lane * 8];
    float4 a1 = *(const float4*)&spanrepr[(size_t)row * 256 + lane * 8 + 4];
    __syncwarp();

#pragma unroll 1
    for (int c = 0; c < 32; ++c) {
        int idx = cidx[warp][c];
        const float4* ep = (const float4*)&ET[(size_t)idx * 256 + lane * 8];
        float4 e0 = ep[0], e1 = ep[1];
        float d = a0.x * e0.x + a0.y * e0.y + a0.z * e0.z + a0.w * e0.w
                + a1.x * e1.x + a1.y * e1.y + a1.z * e1.z + a1.w * e1.w;
#pragma unroll
        for (int o = 16; o; o >>= 1) d += __shfl_xor_sync(0xFFFFFFFFu, d, o);
        if (lane == 0) sims[warp][c] = d;
    }
    __syncwarp();
    if (lane == 0) {
        float tv[8]; int ti[8];
#pragma unroll
        for (int j = 0; j < 8; ++j) { tv[j] = -FLT_MAX; ti[j] = 0x7FFFFFFF; }
        for (int c = 0; c < 32; ++c) insert8(tv, ti, sims[warp][c], cidx[warp][c]);
#pragma unroll
        for (int j = 0; j < 8; ++j) g_topk[(size_t)row * 8 + j] = ti[j];
    }
}

// ------------------------- GCN fused stages ---------------------------------
__global__ void k_gather_mix(const float* __restrict__ b1) {
    int n = blockIdx.x, h = threadIdx.x;
    __shared__ int id[8];
    if (h < 8) id[h] = g_topk[n * 8 + h];
    __syncthreads();
    float bb = b1[h];
    float y0 = g_ybuf[(size_t)id[0] * 256 + h];
    float s = 0.f;
    float* outb = g_hbuf + (size_t)n * 8 * 256 + h;
#pragma unroll
    for (int j = 1; j < 8; ++j) {
        float yj = g_ybuf[(size_t)id[j] * 256 + h];
        s += yj;
        outb[j * 256] = fmaxf(0.25f * y0 + 0.5f * yj + bb, 0.f);
    }
    outb[0] = fmaxf(0.125f * y0 + 0.25f * s + bb, 0.f);
}

__global__ void k_mix_out(const float* __restrict__ b2, float* __restrict__ out_sub) {
    int n = blockIdx.x, h = threadIdx.x;
    const float* inb = g_zbuf + (size_t)n * 8 * 256 + h;
    float* outb = out_sub + (size_t)n * 8 * 256 + h;
    float bb = b2[h];
    float z0 = inb[0];
    float s = 0.f;
#pragma unroll
    for (int j = 1; j < 8; ++j) {
        float zj = inb[j * 256];
        s += zj;
        outb[j * 256] = 0.25f * z0 + 0.5f * zj + bb;
    }
    outb[0] = 0.125f * z0 + 0.25f * s + bb;
}

// ------------------------- host --------------------------------------------
extern "C" void kernel_launch(void* const* d_in, const int* in_sizes, int n_in,
                              void* d_out, int out_size) {
    const float* emb = (const float*)d_in[0];
    const float* ET = (const float*)d_in[1];
    const float* spanW = (const float*)d_in[2];
    const float* spanb = (const float*)d_in[3];
    const float* W1 = (const float*)d_in[4];
    const float* b1 = (const float*)d_in[5];
    const float* W2 = (const float*)d_in[6];
    const float* b2 = (const float*)d_in[7];

    float* out = (float*)d_out;
    float* out_cls = out;                       // 4*256
    float* out_spanrepr = out + 1024;           // 8192*256
    float* out_sub = out + 1024 + 8192 * 256;   // 65536*256

    float *spanmax, *rowbias, *ybuf, *hbuf, *zbuf;
    cudaGetSymbolAddress((void**)&spanmax, g_spanmax);
    cudaGetSymbolAddress((void**)&rowbias, g_rowbias);
    cudaGetSymbolAddress((void**)&ybuf, g_ybuf);
    cudaGetSymbolAddress((void**)&hbuf, g_hbuf);
    cudaGetSymbolAddress((void**)&zbuf, g_zbuf);

    cudaFuncSetAttribute(gemm_k<M_SPAN>, cudaFuncAttributeMaxDynamicSharedMemorySize, SMEM_BYTES);
    cudaFuncSetAttribute(gemm_k<M_PLAIN>, cudaFuncAttributeMaxDynamicSharedMemorySize, SMEM_BYTES);
    cudaFuncSetAttribute(mma_topk, cudaFuncAttributeMaxDynamicSharedMemorySize, MK_SMEM);

    // 1) fused prep: entity bf16 pack + cls/spanmax + rowbias
    k_prep<<<7328, TPB>>>(emb, ET, spanW, spanb, out_cls);
    // 2) span_repr = spanmax @ W[0:256] + rowbias
    gemm_k<M_SPAN><<<256, TPB, SMEM_BYTES>>>(spanmax, spanW, 256, rowbias,
                                             out_spanrepr, NROWS - 1);
    // 3) Y = ET @ W1 (independent of top-k)
    gemm_k<M_PLAIN><<<1568, TPB, SMEM_BYTES>>>(ET, W1, 256, nullptr, ybuf, NE - 1);
    // 4) bf16 mma sims + per-eseg top-16 candidate filter (1024 thr, 48% occ)
    mma_topk<<<dim3(64, 2), 1024, MK_SMEM>>>(out_spanrepr);
    // 5) exact fp32 refine -> sorted top-8
    k_refine<<<1024, 256>>>(out_spanrepr, ET);
    // 6) h = relu(mix(Y[topk]) + b1)
    k_gather_mix<<<NROWS, TPB>>>(b1);
    // 7) Z = h @ W2
    gemm_k<M_PLAIN><<<2048, TPB, SMEM_BYTES>>>(hbuf, W2, 256, nullptr, zbuf, 65535);
    // 8) out_sub = mix(Z) + b2
    k_mix_out<<<NROWS, TPB>>>(b2, out_sub);

    (void)in_sizes; (void)n_in; (void)out_size;
}